// round 2
// baseline (speedup 1.0000x reference)
#include <cuda_runtime.h>
#include <math.h>

// ---------------------------------------------------------------------------
// ViT MHA: B=8, S=1024, D=1024, H=16, hd=64, fp32.
//   1) qkv = x @ w_qkv + b_qkv   -> scatter to q/k/v in [B,H,S,hd], q pre-scaled
//   2) flash attention per (b,h) -> o in [B,S,D]
//   3) out = o @ w_proj + b_proj
// ---------------------------------------------------------------------------

#define NB_HEADS 16
#define HEAD_DIM 64
#define SEQ 1024
#define BATCH 8
#define DMODEL 1024

// Scratch (allocation-free rule: __device__ globals)
__device__ float g_q[(size_t)BATCH * NB_HEADS * SEQ * HEAD_DIM];
__device__ float g_k[(size_t)BATCH * NB_HEADS * SEQ * HEAD_DIM];
__device__ float g_v[(size_t)BATCH * NB_HEADS * SEQ * HEAD_DIM];
__device__ float g_o[(size_t)BATCH * SEQ * DMODEL];

// ---------------------------------------------------------------------------
// GEMM 1: [8192,1024] x [1024,3072] -> scatter into g_q/g_k/g_v
// 128x128 tile, BK=8, 256 threads, 8x8 microtile
// ---------------------------------------------------------------------------
__global__ __launch_bounds__(256) void qkv_gemm(const float* __restrict__ A,
                                                const float* __restrict__ B,
                                                const float* __restrict__ bias) {
    const int K = 1024, N = 3072;
    __shared__ __align__(16) float As[8][128];
    __shared__ __align__(16) float Bs[8][128];

    const int m0 = blockIdx.y * 128;
    const int n0 = blockIdx.x * 128;
    const int tid = threadIdx.x;
    const int ty = tid >> 4, tx = tid & 15;

    const int aRow = tid >> 1;
    const int aCol = (tid & 1) * 4;
    const int bRow = tid >> 5;
    const int bCol = (tid & 31) * 4;

    float acc[8][8];
#pragma unroll
    for (int i = 0; i < 8; i++)
#pragma unroll
        for (int j = 0; j < 8; j++) acc[i][j] = 0.f;

    for (int k0 = 0; k0 < K; k0 += 8) {
        float4 av = *(const float4*)(A + (size_t)(m0 + aRow) * K + k0 + aCol);
        As[aCol + 0][aRow] = av.x;
        As[aCol + 1][aRow] = av.y;
        As[aCol + 2][aRow] = av.z;
        As[aCol + 3][aRow] = av.w;
        float4 bv = *(const float4*)(B + (size_t)(k0 + bRow) * N + n0 + bCol);
        *(float4*)&Bs[bRow][bCol] = bv;
        __syncthreads();
#pragma unroll
        for (int k = 0; k < 8; k++) {
            float a[8], bb[8];
            *(float4*)(a)     = *(const float4*)&As[k][ty * 8];
            *(float4*)(a + 4) = *(const float4*)&As[k][ty * 8 + 4];
            *(float4*)(bb)     = *(const float4*)&Bs[k][tx * 8];
            *(float4*)(bb + 4) = *(const float4*)&Bs[k][tx * 8 + 4];
#pragma unroll
            for (int i = 0; i < 8; i++)
#pragma unroll
                for (int j = 0; j < 8; j++) acc[i][j] += a[i] * bb[j];
        }
        __syncthreads();
    }

    // Epilogue: add bias, scatter to q (scaled by 1/8), k, v in [B,H,S,hd]
#pragma unroll
    for (int i = 0; i < 8; i++) {
        const int row = m0 + ty * 8 + i;
        const int b = row >> 10, s = row & 1023;
#pragma unroll
        for (int j = 0; j < 8; j++) {
            const int n = n0 + tx * 8 + j;
            float v = acc[i][j] + bias[n];
            const int which = n >> 10;
            const int jm = n & 1023;
            const int h = jm >> 6, dd = jm & 63;
            const size_t off = (((size_t)(b * NB_HEADS + h) * SEQ) + s) * HEAD_DIM + dd;
            if (which == 0)      g_q[off] = v * 0.125f;   // fold softmax scale
            else if (which == 1) g_k[off] = v;
            else                 g_v[off] = v;
        }
    }
}

// ---------------------------------------------------------------------------
// Flash attention: one block = (b, h, 64-query tile). 128 threads.
// Sc = Q Kt (64x64x64), online softmax, O += P V (64x64x64).
// ---------------------------------------------------------------------------
#define ATTN_SMEM_FLOATS (3 * 64 * 65 + 64 * 64 + 128)

__global__ __launch_bounds__(128) void attn_kernel() {
    extern __shared__ float sm[];
    float* Qt     = sm;                 // [64][65] transposed (d, q)
    float* Kt     = Qt + 64 * 65;       // [64][65] transposed (d, k)
    float* Ss     = Kt + 64 * 65;       // [64][65] scores (q, k)
    float* Vs     = Ss + 64 * 65;       // [64][64] (k, d)
    float* corr_s = Vs + 64 * 64;       // [64]
    float* l_s    = corr_s + 64;        // [64]

    const int tid = threadIdx.x;
    const int q0 = blockIdx.x * 64;
    const int h = blockIdx.y, b = blockIdx.z;

    const size_t bh = (size_t)(b * NB_HEADS + h) * SEQ * HEAD_DIM;
    const float* qb = g_q + bh;
    const float* kb = g_k + bh;
    const float* vb = g_v + bh;

    // load Q tile transposed
    for (int i = tid; i < 64 * 64; i += 128) {
        const int q = i >> 6, d = i & 63;
        Qt[d * 65 + q] = qb[(size_t)(q0 + q) * 64 + d];
    }

    const int ty = tid >> 4, tx = tid & 15;   // 8 x 16 thread grid
    float o[8][4];
#pragma unroll
    for (int i = 0; i < 8; i++)
#pragma unroll
        for (int j = 0; j < 4; j++) o[i][j] = 0.f;

    float m = -1e30f, l = 0.f;   // valid for tid < 64

    for (int k0 = 0; k0 < SEQ; k0 += 64) {
        __syncthreads();   // protect smem from previous iteration / Q load
        for (int i = tid; i < 64 * 64; i += 128) {
            const int kk = i >> 6, d = i & 63;
            Kt[d * 65 + kk] = kb[(size_t)(k0 + kk) * 64 + d];
            Vs[i]           = vb[(size_t)(k0 + kk) * 64 + d];
        }
        __syncthreads();

        // scores: sc[i][j] = sum_d Qt[d][ty*8+i] * Kt[d][tx*4+j]
        float sc[8][4];
#pragma unroll
        for (int i = 0; i < 8; i++)
#pragma unroll
            for (int j = 0; j < 4; j++) sc[i][j] = 0.f;
#pragma unroll 4
        for (int d = 0; d < 64; d++) {
            float a[8], bb[4];
#pragma unroll
            for (int i = 0; i < 8; i++) a[i] = Qt[d * 65 + ty * 8 + i];
#pragma unroll
            for (int j = 0; j < 4; j++) bb[j] = Kt[d * 65 + tx * 4 + j];
#pragma unroll
            for (int i = 0; i < 8; i++)
#pragma unroll
                for (int j = 0; j < 4; j++) sc[i][j] += a[i] * bb[j];
        }
#pragma unroll
        for (int i = 0; i < 8; i++)
#pragma unroll
            for (int j = 0; j < 4; j++)
                Ss[(ty * 8 + i) * 65 + tx * 4 + j] = sc[i][j];
        __syncthreads();

        // online softmax, one thread per query row
        if (tid < 64) {
            float* row = Ss + tid * 65;
            float mnew = m;
#pragma unroll 8
            for (int c = 0; c < 64; c++) mnew = fmaxf(mnew, row[c]);
            const float corr = __expf(m - mnew);
            float ls = 0.f;
#pragma unroll 8
            for (int c = 0; c < 64; c++) {
                const float p = __expf(row[c] - mnew);
                row[c] = p;
                ls += p;
            }
            l = l * corr + ls;
            m = mnew;
            corr_s[tid] = corr;
        }
        __syncthreads();

        // rescale O and accumulate P @ V
        float cf[8];
#pragma unroll
        for (int i = 0; i < 8; i++) cf[i] = corr_s[ty * 8 + i];
#pragma unroll
        for (int i = 0; i < 8; i++)
#pragma unroll
            for (int j = 0; j < 4; j++) o[i][j] *= cf[i];
#pragma unroll 4
        for (int kk = 0; kk < 64; kk++) {
            float a[8], bb[4];
#pragma unroll
            for (int i = 0; i < 8; i++) a[i] = Ss[(ty * 8 + i) * 65 + kk];
#pragma unroll
            for (int j = 0; j < 4; j++) bb[j] = Vs[kk * 64 + tx * 4 + j];
#pragma unroll
            for (int i = 0; i < 8; i++)
#pragma unroll
                for (int j = 0; j < 4; j++) o[i][j] += a[i] * bb[j];
        }
    }

    if (tid < 64) l_s[tid] = l;
    __syncthreads();

    float li[8];
#pragma unroll
    for (int i = 0; i < 8; i++) li[i] = 1.f / l_s[ty * 8 + i];
#pragma unroll
    for (int i = 0; i < 8; i++) {
        const int s = q0 + ty * 8 + i;
#pragma unroll
        for (int j = 0; j < 4; j++) {
            g_o[((size_t)b * SEQ + s) * DMODEL + h * HEAD_DIM + tx * 4 + j] =
                o[i][j] * li[i];
        }
    }
}

// ---------------------------------------------------------------------------
// GEMM 2: [8192,1024] x [1024,1024] + bias -> out
// ---------------------------------------------------------------------------
__global__ __launch_bounds__(256) void proj_gemm(const float* __restrict__ B,
                                                 const float* __restrict__ bias,
                                                 float* __restrict__ out) {
    const int K = 1024, N = 1024;
    __shared__ __align__(16) float As[8][128];
    __shared__ __align__(16) float Bs[8][128];

    const int m0 = blockIdx.y * 128;
    const int n0 = blockIdx.x * 128;
    const int tid = threadIdx.x;
    const int ty = tid >> 4, tx = tid & 15;

    const int aRow = tid >> 1;
    const int aCol = (tid & 1) * 4;
    const int bRow = tid >> 5;
    const int bCol = (tid & 31) * 4;

    const float* A = g_o;

    float acc[8][8];
#pragma unroll
    for (int i = 0; i < 8; i++)
#pragma unroll
        for (int j = 0; j < 8; j++) acc[i][j] = 0.f;

    for (int k0 = 0; k0 < K; k0 += 8) {
        float4 av = *(const float4*)(A + (size_t)(m0 + aRow) * K + k0 + aCol);
        As[aCol + 0][aRow] = av.x;
        As[aCol + 1][aRow] = av.y;
        As[aCol + 2][aRow] = av.z;
        As[aCol + 3][aRow] = av.w;
        float4 bv = *(const float4*)(B + (size_t)(k0 + bRow) * N + n0 + bCol);
        *(float4*)&Bs[bRow][bCol] = bv;
        __syncthreads();
#pragma unroll
        for (int k = 0; k < 8; k++) {
            float a[8], bb[8];
            *(float4*)(a)     = *(const float4*)&As[k][ty * 8];
            *(float4*)(a + 4) = *(const float4*)&As[k][ty * 8 + 4];
            *(float4*)(bb)     = *(const float4*)&Bs[k][tx * 8];
            *(float4*)(bb + 4) = *(const float4*)&Bs[k][tx * 8 + 4];
#pragma unroll
            for (int i = 0; i < 8; i++)
#pragma unroll
                for (int j = 0; j < 8; j++) acc[i][j] += a[i] * bb[j];
        }
        __syncthreads();
    }

#pragma unroll
    for (int i = 0; i < 8; i++) {
        const int row = m0 + ty * 8 + i;
#pragma unroll
        for (int j = 0; j < 8; j++) {
            const int n = n0 + tx * 8 + j;
            out[(size_t)row * N + n] = acc[i][j] + bias[n];
        }
    }
}

// ---------------------------------------------------------------------------

extern "C" void kernel_launch(void* const* d_in, const int* in_sizes, int n_in,
                              void* d_out, int out_size) {
    const float* x      = (const float*)d_in[0];
    const float* w_qkv  = (const float*)d_in[1];
    const float* b_qkv  = (const float*)d_in[2];
    const float* w_proj = (const float*)d_in[3];
    const float* b_proj = (const float*)d_in[4];
    float* out = (float*)d_out;

    const int attn_smem = ATTN_SMEM_FLOATS * (int)sizeof(float);
    cudaFuncSetAttribute(attn_kernel,
                         cudaFuncAttributeMaxDynamicSharedMemorySize, attn_smem);

    {
        dim3 grid(3072 / 128, 8192 / 128);
        qkv_gemm<<<grid, 256>>>(x, w_qkv, b_qkv);
    }
    {
        dim3 grid(SEQ / 64, NB_HEADS, BATCH);
        attn_kernel<<<grid, 128, attn_smem>>>();
    }
    {
        dim3 grid(1024 / 128, 8192 / 128);
        proj_gemm<<<grid, 256>>>(w_proj, b_proj, out);
    }
}

// round 4
// speedup vs baseline: 1.1898x; 1.1898x over previous
#include <cuda_runtime.h>
#include <cuda.h>
#include <cstdint>
#include <math.h>

// ---------------------------------------------------------------------------
// ViT MHA B=8, S=1024, D=1024, H=16, hd=64 (fp32 in/out).
// R4: GEMMs via mma.sync m16n8k8 tf32 (baseline PTX -> legacy HMMA on sm_103a;
//     tcgen05 PTX is rejected by this harness's compute_103 target).
//     Flash attention still SIMT (next target).
// ---------------------------------------------------------------------------

#define NB_HEADS 16
#define HEAD_DIM 64
#define SEQ 1024
#define BATCH 8
#define DMODEL 1024

__device__ float g_q[(size_t)BATCH * NB_HEADS * SEQ * HEAD_DIM];
__device__ float g_k[(size_t)BATCH * NB_HEADS * SEQ * HEAD_DIM];
__device__ float g_v[(size_t)BATCH * NB_HEADS * SEQ * HEAD_DIM];
__device__ float g_o[(size_t)BATCH * SEQ * DMODEL];
__device__ float g_wqkvT[(size_t)3072 * 1024];   // [N][K] K-major
__device__ float g_wprojT[(size_t)1024 * 1024];  // [N][K] K-major

// ------------------------------ helpers ------------------------------------
__device__ __forceinline__ uint32_t smem_u32(const void* p) {
    uint32_t a;
    asm("{ .reg .u64 t; cvta.to.shared.u64 t, %1; cvt.u32.u64 %0, t; }"
        : "=r"(a) : "l"(p));
    return a;
}

__device__ __forceinline__ uint32_t f2tf32(float f) {
    uint32_t u;
    asm("cvt.rna.tf32.f32 %0, %1;" : "=r"(u) : "f"(f));
    return u;
}

__device__ __forceinline__ void cp_async16(uint32_t dst, const void* src) {
    asm volatile("cp.async.ca.shared.global [%0], [%1], 16;"
                 :: "r"(dst), "l"(src) : "memory");
}
__device__ __forceinline__ void cp_commit() {
    asm volatile("cp.async.commit_group;" ::: "memory");
}
__device__ __forceinline__ void cp_wait0() {
    asm volatile("cp.async.wait_group 0;" ::: "memory");
}

__device__ __forceinline__ void mma_tf32(float& c0, float& c1, float& c2, float& c3,
                                         uint32_t a0, uint32_t a1, uint32_t a2,
                                         uint32_t a3, uint32_t b0, uint32_t b1) {
    asm volatile(
        "mma.sync.aligned.m16n8k8.row.col.f32.tf32.tf32.f32 "
        "{%0,%1,%2,%3}, {%4,%5,%6,%7}, {%8,%9}, {%0,%1,%2,%3};"
        : "+f"(c0), "+f"(c1), "+f"(c2), "+f"(c3)
        : "r"(a0), "r"(a1), "r"(a2), "r"(a3), "r"(b0), "r"(b1));
}

// ---------------------------------------------------------------------------
// Weight transpose: out[n][k] = in[k][n].  in is [1024][C].
// ---------------------------------------------------------------------------
__global__ __launch_bounds__(256) void transpose_kernel(const float* __restrict__ in,
                                                        int C, int which) {
    __shared__ float t[32][33];
    float* out = which ? g_wprojT : g_wqkvT;
    const int R = 1024;
    const int c0 = blockIdx.x * 32, r0 = blockIdx.y * 32;
    const int tx = threadIdx.x, ty = threadIdx.y;  // 32 x 8
#pragma unroll
    for (int i = 0; i < 32; i += 8)
        t[ty + i][tx] = in[(size_t)(r0 + ty + i) * C + c0 + tx];
    __syncthreads();
#pragma unroll
    for (int i = 0; i < 32; i += 8)
        out[(size_t)(c0 + ty + i) * R + r0 + tx] = t[tx][ty + i];
}

// ---------------------------------------------------------------------------
// mma.sync tf32 GEMM: C[128x128] = A[m0:,1024] x BT[n0:,1024]^T
// 256 threads, 8 warps in 2x4; warp tile 64x32 = 4x4 mma(16x8) tiles; BK=32.
// Smem rows padded to 36 floats -> fragment LDS conflict-free (4g+tig).
// mode 0: A=x, BT=g_wqkvT, scatter epilogue to g_q/g_k/g_v (+bias, q*0.125)
// mode 1: A=g_o, BT=g_wprojT, epilogue writes Cout (+bias)
// ---------------------------------------------------------------------------
#define PAD 36
#define GEMM_SMEM_BYTES (2 * 2 * 128 * PAD * 4)   // A/B x double buffer = 73728

__global__ __launch_bounds__(256) void gemm_mma(const float* __restrict__ A_ext,
                                                const float* __restrict__ bias,
                                                float* __restrict__ Cout, int mode) {
    extern __shared__ __align__(16) float sm[];
    float* As = sm;                        // [2][128][PAD]
    float* Bs = sm + 2 * 128 * PAD;        // [2][128][PAD]
    const uint32_t sA = smem_u32(As), sB = smem_u32(Bs);

    const float* A  = mode ? g_o      : A_ext;
    const float* BT = mode ? g_wprojT : g_wqkvT;

    const int m0 = blockIdx.y * 128;
    const int n0 = blockIdx.x * 128;
    const int tid = threadIdx.x;
    const int warp = tid >> 5, lane = tid & 31;
    const int g = lane >> 2, tig = lane & 3;
    const int wm = (warp >> 2) * 64;   // warp row offset in tile
    const int wn = (warp & 3) * 32;    // warp col offset in tile

    // global->smem copy mapping: 1024 float4 per (A|B) buffer, 4 per thread
    const int cpRow = tid >> 1;              // 0..127 (2 threads/row, 2 float4 each... )
    // Actually: idx = tid + i*256; row = idx>>3; col4 = idx&7.

    float c[4][4][4];
#pragma unroll
    for (int i = 0; i < 4; i++)
#pragma unroll
        for (int j = 0; j < 4; j++)
#pragma unroll
            for (int r = 0; r < 4; r++) c[i][j][r] = 0.f;

    (void)cpRow;

    auto prefetch = [&](int buf, int kc) {
        const float* Ag = A  + (size_t)m0 * 1024 + kc * 32;
        const float* Bg = BT + (size_t)n0 * 1024 + kc * 32;
        const uint32_t aBase = sA + buf * 128 * PAD * 4;
        const uint32_t bBase = sB + buf * 128 * PAD * 4;
#pragma unroll
        for (int i = 0; i < 4; i++) {
            const int idx = tid + i * 256;
            const int row = idx >> 3, c4 = idx & 7;
            const uint32_t so = (uint32_t)(row * PAD + c4 * 4) * 4;
            cp_async16(aBase + so, Ag + (size_t)row * 1024 + c4 * 4);
            cp_async16(bBase + so, Bg + (size_t)row * 1024 + c4 * 4);
        }
        cp_commit();
    };

    prefetch(0, 0);

    for (int kc = 0; kc < 32; kc++) {
        const int p = kc & 1;
        cp_wait0();
        __syncthreads();
        if (kc < 31) prefetch(p ^ 1, kc + 1);

        const float* Ab = As + p * 128 * PAD;
        const float* Bb = Bs + p * 128 * PAD;

#pragma unroll
        for (int ks = 0; ks < 4; ks++) {
            const int kk = ks * 8;
            uint32_t a[4][4], b[4][2];
#pragma unroll
            for (int mt = 0; mt < 4; mt++) {
                const int r0 = wm + mt * 16 + g;
                a[mt][0] = f2tf32(Ab[r0 * PAD + kk + tig]);
                a[mt][1] = f2tf32(Ab[(r0 + 8) * PAD + kk + tig]);
                a[mt][2] = f2tf32(Ab[r0 * PAD + kk + tig + 4]);
                a[mt][3] = f2tf32(Ab[(r0 + 8) * PAD + kk + tig + 4]);
            }
#pragma unroll
            for (int nt = 0; nt < 4; nt++) {
                const int nr = wn + nt * 8 + g;
                b[nt][0] = f2tf32(Bb[nr * PAD + kk + tig]);
                b[nt][1] = f2tf32(Bb[nr * PAD + kk + tig + 4]);
            }
#pragma unroll
            for (int mt = 0; mt < 4; mt++)
#pragma unroll
                for (int nt = 0; nt < 4; nt++)
                    mma_tf32(c[mt][nt][0], c[mt][nt][1], c[mt][nt][2], c[mt][nt][3],
                             a[mt][0], a[mt][1], a[mt][2], a[mt][3],
                             b[nt][0], b[nt][1]);
        }
        __syncthreads();
    }

    // Epilogue: c0/c1 at (row g, cols 2tig,2tig+1), c2/c3 at row g+8.
#pragma unroll
    for (int mt = 0; mt < 4; mt++) {
#pragma unroll
        for (int nt = 0; nt < 4; nt++) {
            const int rowA = m0 + wm + mt * 16 + g;
            const int rowB = rowA + 8;
            const int n = n0 + wn + nt * 8 + 2 * tig;
            const float b0 = bias[n], b1 = bias[n + 1];
            if (mode == 1) {
                float2 v0 = make_float2(c[mt][nt][0] + b0, c[mt][nt][1] + b1);
                float2 v1 = make_float2(c[mt][nt][2] + b0, c[mt][nt][3] + b1);
                *(float2*)(Cout + (size_t)rowA * 1024 + n) = v0;
                *(float2*)(Cout + (size_t)rowB * 1024 + n) = v1;
            } else {
                const int which = n >> 10;
                const int nm = n & 1023;
                const int h = nm >> 6, dd = nm & 63;
                float* dst = (which == 0) ? g_q : (which == 1) ? g_k : g_v;
                const float sc = (which == 0) ? 0.125f : 1.f;
                const int bA = rowA >> 10, sAr = rowA & 1023;
                const int bB = rowB >> 10, sBr = rowB & 1023;
                const size_t offA =
                    (((size_t)(bA * NB_HEADS + h) * SEQ) + sAr) * HEAD_DIM + dd;
                const size_t offB =
                    (((size_t)(bB * NB_HEADS + h) * SEQ) + sBr) * HEAD_DIM + dd;
                *(float2*)(dst + offA) =
                    make_float2((c[mt][nt][0] + b0) * sc, (c[mt][nt][1] + b1) * sc);
                *(float2*)(dst + offB) =
                    make_float2((c[mt][nt][2] + b0) * sc, (c[mt][nt][3] + b1) * sc);
            }
        }
    }
}

// ---------------------------------------------------------------------------
// Flash attention (verified SIMT version): one block = (b, h, 64-query tile).
// ---------------------------------------------------------------------------
#define ATTN_SMEM_FLOATS (3 * 64 * 65 + 64 * 64 + 128)

__global__ __launch_bounds__(128) void attn_kernel() {
    extern __shared__ float sm[];
    float* Qt     = sm;
    float* Kt     = Qt + 64 * 65;
    float* Ss     = Kt + 64 * 65;
    float* Vs     = Ss + 64 * 65;
    float* corr_s = Vs + 64 * 64;
    float* l_s    = corr_s + 64;

    const int tid = threadIdx.x;
    const int q0 = blockIdx.x * 64;
    const int h = blockIdx.y, b = blockIdx.z;

    const size_t bh = (size_t)(b * NB_HEADS + h) * SEQ * HEAD_DIM;
    const float* qb = g_q + bh;
    const float* kb = g_k + bh;
    const float* vb = g_v + bh;

    for (int i = tid; i < 64 * 64; i += 128) {
        const int q = i >> 6, d = i & 63;
        Qt[d * 65 + q] = qb[(size_t)(q0 + q) * 64 + d];
    }

    const int ty = tid >> 4, tx = tid & 15;
    float o[8][4];
#pragma unroll
    for (int i = 0; i < 8; i++)
#pragma unroll
        for (int j = 0; j < 4; j++) o[i][j] = 0.f;

    float m = -1e30f, l = 0.f;

    for (int k0 = 0; k0 < SEQ; k0 += 64) {
        __syncthreads();
        for (int i = tid; i < 64 * 64; i += 128) {
            const int kk = i >> 6, d = i & 63;
            Kt[d * 65 + kk] = kb[(size_t)(k0 + kk) * 64 + d];
            Vs[i]           = vb[(size_t)(k0 + kk) * 64 + d];
        }
        __syncthreads();

        float sc[8][4];
#pragma unroll
        for (int i = 0; i < 8; i++)
#pragma unroll
            for (int j = 0; j < 4; j++) sc[i][j] = 0.f;
#pragma unroll 4
        for (int d = 0; d < 64; d++) {
            float a[8], bb[4];
#pragma unroll
            for (int i = 0; i < 8; i++) a[i] = Qt[d * 65 + ty * 8 + i];
#pragma unroll
            for (int j = 0; j < 4; j++) bb[j] = Kt[d * 65 + tx * 4 + j];
#pragma unroll
            for (int i = 0; i < 8; i++)
#pragma unroll
                for (int j = 0; j < 4; j++) sc[i][j] += a[i] * bb[j];
        }
#pragma unroll
        for (int i = 0; i < 8; i++)
#pragma unroll
            for (int j = 0; j < 4; j++)
                Ss[(ty * 8 + i) * 65 + tx * 4 + j] = sc[i][j];
        __syncthreads();

        if (tid < 64) {
            float* row = Ss + tid * 65;
            float mnew = m;
#pragma unroll 8
            for (int c = 0; c < 64; c++) mnew = fmaxf(mnew, row[c]);
            const float corr = __expf(m - mnew);
            float ls = 0.f;
#pragma unroll 8
            for (int c = 0; c < 64; c++) {
                const float p = __expf(row[c] - mnew);
                row[c] = p;
                ls += p;
            }
            l = l * corr + ls;
            m = mnew;
            corr_s[tid] = corr;
        }
        __syncthreads();

        float cf[8];
#pragma unroll
        for (int i = 0; i < 8; i++) cf[i] = corr_s[ty * 8 + i];
#pragma unroll
        for (int i = 0; i < 8; i++)
#pragma unroll
            for (int j = 0; j < 4; j++) o[i][j] *= cf[i];
#pragma unroll 4
        for (int kk = 0; kk < 64; kk++) {
            float a[8], bb[4];
#pragma unroll
            for (int i = 0; i < 8; i++) a[i] = Ss[(ty * 8 + i) * 65 + kk];
#pragma unroll
            for (int j = 0; j < 4; j++) bb[j] = Vs[kk * 64 + tx * 4 + j];
#pragma unroll
            for (int i = 0; i < 8; i++)
#pragma unroll
                for (int j = 0; j < 4; j++) o[i][j] += a[i] * bb[j];
        }
    }

    if (tid < 64) l_s[tid] = l;
    __syncthreads();

    float li[8];
#pragma unroll
    for (int i = 0; i < 8; i++) li[i] = 1.f / l_s[ty * 8 + i];
#pragma unroll
    for (int i = 0; i < 8; i++) {
        const int s = q0 + ty * 8 + i;
#pragma unroll
        for (int j = 0; j < 4; j++) {
            g_o[((size_t)b * SEQ + s) * DMODEL + h * HEAD_DIM + tx * 4 + j] =
                o[i][j] * li[i];
        }
    }
}

// ---------------------------------------------------------------------------

extern "C" void kernel_launch(void* const* d_in, const int* in_sizes, int n_in,
                              void* d_out, int out_size) {
    (void)in_sizes; (void)n_in; (void)out_size;
    const float* x      = (const float*)d_in[0];
    const float* w_qkv  = (const float*)d_in[1];
    const float* b_qkv  = (const float*)d_in[2];
    const float* w_proj = (const float*)d_in[3];
    const float* b_proj = (const float*)d_in[4];
    float* out = (float*)d_out;

    cudaFuncSetAttribute(gemm_mma, cudaFuncAttributeMaxDynamicSharedMemorySize,
                         GEMM_SMEM_BYTES);
    const int attn_smem = ATTN_SMEM_FLOATS * (int)sizeof(float);
    cudaFuncSetAttribute(attn_kernel, cudaFuncAttributeMaxDynamicSharedMemorySize,
                         attn_smem);

    transpose_kernel<<<dim3(96, 32), dim3(32, 8)>>>(w_qkv, 3072, 0);
    transpose_kernel<<<dim3(32, 32), dim3(32, 8)>>>(w_proj, 1024, 1);

    gemm_mma<<<dim3(24, 64), 256, GEMM_SMEM_BYTES>>>(x, b_qkv, nullptr, 0);

    attn_kernel<<<dim3(SEQ / 64, NB_HEADS, BATCH), 128, attn_smem>>>();

    gemm_mma<<<dim3(8, 64), 256, GEMM_SMEM_BYTES>>>(nullptr, b_proj, out, 1);
}

// round 5
// speedup vs baseline: 2.6792x; 2.2518x over previous
#include <cuda_runtime.h>
#include <cuda.h>
#include <cstdint>
#include <math.h>

// ---------------------------------------------------------------------------
// ViT MHA B=8, S=1024, D=1024, H=16, hd=64 (fp32 in/out).
// R5: attention moved to mma.sync m16n8k8 tf32 (FA2-style fragment softmax,
//     split-tf32 for QK^T to protect the error budget). GEMMs as in R4.
// ---------------------------------------------------------------------------

#define NB_HEADS 16
#define HEAD_DIM 64
#define SEQ 1024
#define BATCH 8
#define DMODEL 1024

__device__ float g_q[(size_t)BATCH * NB_HEADS * SEQ * HEAD_DIM];
__device__ float g_k[(size_t)BATCH * NB_HEADS * SEQ * HEAD_DIM];
__device__ float g_v[(size_t)BATCH * NB_HEADS * SEQ * HEAD_DIM];
__device__ float g_o[(size_t)BATCH * SEQ * DMODEL];
__device__ float g_wqkvT[(size_t)3072 * 1024];   // [N][K] K-major
__device__ float g_wprojT[(size_t)1024 * 1024];  // [N][K] K-major

// ------------------------------ helpers ------------------------------------
__device__ __forceinline__ uint32_t smem_u32(const void* p) {
    uint32_t a;
    asm("{ .reg .u64 t; cvta.to.shared.u64 t, %1; cvt.u32.u64 %0, t; }"
        : "=r"(a) : "l"(p));
    return a;
}

__device__ __forceinline__ uint32_t f2tf32(float f) {
    uint32_t u;
    asm("cvt.rna.tf32.f32 %0, %1;" : "=r"(u) : "f"(f));
    return u;
}

__device__ __forceinline__ void cp_async16(uint32_t dst, const void* src) {
    asm volatile("cp.async.ca.shared.global [%0], [%1], 16;"
                 :: "r"(dst), "l"(src) : "memory");
}
__device__ __forceinline__ void cp_commit() {
    asm volatile("cp.async.commit_group;" ::: "memory");
}
__device__ __forceinline__ void cp_wait0() {
    asm volatile("cp.async.wait_group 0;" ::: "memory");
}

__device__ __forceinline__ void mma_tf32(float& c0, float& c1, float& c2, float& c3,
                                         uint32_t a0, uint32_t a1, uint32_t a2,
                                         uint32_t a3, uint32_t b0, uint32_t b1) {
    asm volatile(
        "mma.sync.aligned.m16n8k8.row.col.f32.tf32.tf32.f32 "
        "{%0,%1,%2,%3}, {%4,%5,%6,%7}, {%8,%9}, {%0,%1,%2,%3};"
        : "+f"(c0), "+f"(c1), "+f"(c2), "+f"(c3)
        : "r"(a0), "r"(a1), "r"(a2), "r"(a3), "r"(b0), "r"(b1));
}

// ---------------------------------------------------------------------------
// Weight transpose: out[n][k] = in[k][n].  in is [1024][C].
// ---------------------------------------------------------------------------
__global__ __launch_bounds__(256) void transpose_kernel(const float* __restrict__ in,
                                                        int C, int which) {
    __shared__ float t[32][33];
    float* out = which ? g_wprojT : g_wqkvT;
    const int R = 1024;
    const int c0 = blockIdx.x * 32, r0 = blockIdx.y * 32;
    const int tx = threadIdx.x, ty = threadIdx.y;  // 32 x 8
#pragma unroll
    for (int i = 0; i < 32; i += 8)
        t[ty + i][tx] = in[(size_t)(r0 + ty + i) * C + c0 + tx];
    __syncthreads();
#pragma unroll
    for (int i = 0; i < 32; i += 8)
        out[(size_t)(c0 + ty + i) * R + r0 + tx] = t[tx][ty + i];
}

// ---------------------------------------------------------------------------
// mma.sync tf32 GEMM (unchanged from R4): C[128x128] = A x BT^T, K=1024.
// ---------------------------------------------------------------------------
#define PAD 36
#define GEMM_SMEM_BYTES (2 * 2 * 128 * PAD * 4)

__global__ __launch_bounds__(256) void gemm_mma(const float* __restrict__ A_ext,
                                                const float* __restrict__ bias,
                                                float* __restrict__ Cout, int mode) {
    extern __shared__ __align__(16) float sm[];
    float* As = sm;
    float* Bs = sm + 2 * 128 * PAD;
    const uint32_t sA = smem_u32(As), sB = smem_u32(Bs);

    const float* A  = mode ? g_o      : A_ext;
    const float* BT = mode ? g_wprojT : g_wqkvT;

    const int m0 = blockIdx.y * 128;
    const int n0 = blockIdx.x * 128;
    const int tid = threadIdx.x;
    const int warp = tid >> 5, lane = tid & 31;
    const int g = lane >> 2, tig = lane & 3;
    const int wm = (warp >> 2) * 64;
    const int wn = (warp & 3) * 32;

    float c[4][4][4];
#pragma unroll
    for (int i = 0; i < 4; i++)
#pragma unroll
        for (int j = 0; j < 4; j++)
#pragma unroll
            for (int r = 0; r < 4; r++) c[i][j][r] = 0.f;

    auto prefetch = [&](int buf, int kc) {
        const float* Ag = A  + (size_t)m0 * 1024 + kc * 32;
        const float* Bg = BT + (size_t)n0 * 1024 + kc * 32;
        const uint32_t aBase = sA + buf * 128 * PAD * 4;
        const uint32_t bBase = sB + buf * 128 * PAD * 4;
#pragma unroll
        for (int i = 0; i < 4; i++) {
            const int idx = tid + i * 256;
            const int row = idx >> 3, c4 = idx & 7;
            const uint32_t so = (uint32_t)(row * PAD + c4 * 4) * 4;
            cp_async16(aBase + so, Ag + (size_t)row * 1024 + c4 * 4);
            cp_async16(bBase + so, Bg + (size_t)row * 1024 + c4 * 4);
        }
        cp_commit();
    };

    prefetch(0, 0);

    for (int kc = 0; kc < 32; kc++) {
        const int p = kc & 1;
        cp_wait0();
        __syncthreads();
        if (kc < 31) prefetch(p ^ 1, kc + 1);

        const float* Ab = As + p * 128 * PAD;
        const float* Bb = Bs + p * 128 * PAD;

#pragma unroll
        for (int ks = 0; ks < 4; ks++) {
            const int kk = ks * 8;
            uint32_t a[4][4], b[4][2];
#pragma unroll
            for (int mt = 0; mt < 4; mt++) {
                const int r0 = wm + mt * 16 + g;
                a[mt][0] = f2tf32(Ab[r0 * PAD + kk + tig]);
                a[mt][1] = f2tf32(Ab[(r0 + 8) * PAD + kk + tig]);
                a[mt][2] = f2tf32(Ab[r0 * PAD + kk + tig + 4]);
                a[mt][3] = f2tf32(Ab[(r0 + 8) * PAD + kk + tig + 4]);
            }
#pragma unroll
            for (int nt = 0; nt < 4; nt++) {
                const int nr = wn + nt * 8 + g;
                b[nt][0] = f2tf32(Bb[nr * PAD + kk + tig]);
                b[nt][1] = f2tf32(Bb[nr * PAD + kk + tig + 4]);
            }
#pragma unroll
            for (int mt = 0; mt < 4; mt++)
#pragma unroll
                for (int nt = 0; nt < 4; nt++)
                    mma_tf32(c[mt][nt][0], c[mt][nt][1], c[mt][nt][2], c[mt][nt][3],
                             a[mt][0], a[mt][1], a[mt][2], a[mt][3],
                             b[nt][0], b[nt][1]);
        }
        __syncthreads();
    }

#pragma unroll
    for (int mt = 0; mt < 4; mt++) {
#pragma unroll
        for (int nt = 0; nt < 4; nt++) {
            const int rowA = m0 + wm + mt * 16 + g;
            const int rowB = rowA + 8;
            const int n = n0 + wn + nt * 8 + 2 * tig;
            const float b0 = bias[n], b1 = bias[n + 1];
            if (mode == 1) {
                *(float2*)(Cout + (size_t)rowA * 1024 + n) =
                    make_float2(c[mt][nt][0] + b0, c[mt][nt][1] + b1);
                *(float2*)(Cout + (size_t)rowB * 1024 + n) =
                    make_float2(c[mt][nt][2] + b0, c[mt][nt][3] + b1);
            } else {
                const int which = n >> 10;
                const int nm = n & 1023;
                const int h = nm >> 6, dd = nm & 63;
                float* dst = (which == 0) ? g_q : (which == 1) ? g_k : g_v;
                const float sc = (which == 0) ? 0.125f : 1.f;
                const int bA = rowA >> 10, sAr = rowA & 1023;
                const int bB = rowB >> 10, sBr = rowB & 1023;
                const size_t offA =
                    (((size_t)(bA * NB_HEADS + h) * SEQ) + sAr) * HEAD_DIM + dd;
                const size_t offB =
                    (((size_t)(bB * NB_HEADS + h) * SEQ) + sBr) * HEAD_DIM + dd;
                *(float2*)(dst + offA) =
                    make_float2((c[mt][nt][0] + b0) * sc, (c[mt][nt][1] + b1) * sc);
                *(float2*)(dst + offB) =
                    make_float2((c[mt][nt][2] + b0) * sc, (c[mt][nt][3] + b1) * sc);
            }
        }
    }
}

// ---------------------------------------------------------------------------
// Tensor-core flash attention.
// Block = (128 queries) x (b,h). 256 threads = 8 warps, warp owns 16 q-rows.
// S = Q K^T (split-tf32, 3 mma), fragment online softmax, P via smem,
// O += P V^T (plain tf32). K/V tiles of 64 keys.
// ---------------------------------------------------------------------------
#define PADA 68
#define ATTN_SMEM_BYTES ((128 * PADA + 64 * PADA + 64 * PADA + 128 * PADA) * 4)

__global__ __launch_bounds__(256, 2) void attn_mma() {
    extern __shared__ __align__(16) float smf[];
    float* Qs = smf;                       // [128][PADA] (q, d)
    float* Ks = Qs + 128 * PADA;           // [64][PADA]  (key, d)
    float* Vt = Ks + 64 * PADA;            // [64][PADA]  (d, key)
    float* Ps = Vt + 64 * PADA;            // [128][PADA] (q, key)
    const uint32_t sQ = smem_u32(Qs), sK = smem_u32(Ks);

    const int tid = threadIdx.x;
    const int warp = tid >> 5, lane = tid & 31;
    const int g = lane >> 2, tig = lane & 3;
    const int wb = warp * 16;

    const int q0 = blockIdx.x * 128;
    const int h = blockIdx.y, b = blockIdx.z;
    const size_t bh = (size_t)(b * NB_HEADS + h) * SEQ * HEAD_DIM;
    const float* qb = g_q + bh;
    const float* kb = g_k + bh;
    const float* vb = g_v + bh;

    // prefetch Q tile (128 x 64): 2048 float4, 8 per thread
#pragma unroll
    for (int i = 0; i < 8; i++) {
        const int idx = tid + i * 256;
        const int row = idx >> 4, c4 = idx & 15;
        cp_async16(sQ + (uint32_t)(row * PADA + c4 * 4) * 4,
                   qb + (size_t)(q0 + row) * 64 + c4 * 4);
    }
    cp_commit();

    float o[8][4];
#pragma unroll
    for (int nt = 0; nt < 8; nt++)
#pragma unroll
        for (int r = 0; r < 4; r++) o[nt][r] = 0.f;
    float m0 = -1e30f, m1 = -1e30f, l0 = 0.f, l1 = 0.f;

    for (int kb0 = 0; kb0 < 16; kb0++) {
        const int k0 = kb0 * 64;
        __syncthreads();   // previous iteration done reading Ks/Vt

        // K tile (64 x 64) via cp.async: 1024 float4, 4/thread
#pragma unroll
        for (int i = 0; i < 4; i++) {
            const int idx = tid + i * 256;
            const int row = idx >> 4, c4 = idx & 15;
            cp_async16(sK + (uint32_t)(row * PADA + c4 * 4) * 4,
                       kb + (size_t)(k0 + row) * 64 + c4 * 4);
        }
        cp_commit();

        // V tile transposed: row = idx&63 keeps STS conflict-free
#pragma unroll
        for (int i = 0; i < 4; i++) {
            const int idx = tid + i * 256;
            const int row = idx & 63, c4 = idx >> 6;
            float4 v = *(const float4*)(vb + (size_t)(k0 + row) * 64 + c4 * 4);
            Vt[(c4 * 4 + 0) * PADA + row] = v.x;
            Vt[(c4 * 4 + 1) * PADA + row] = v.y;
            Vt[(c4 * 4 + 2) * PADA + row] = v.z;
            Vt[(c4 * 4 + 3) * PADA + row] = v.w;
        }
        cp_wait0();
        __syncthreads();

        // ---- S = Q K^T  (split-tf32: hi*hi + hi*lo + lo*hi) ----
        float s[8][4];
#pragma unroll
        for (int nt = 0; nt < 8; nt++)
#pragma unroll
            for (int r = 0; r < 4; r++) s[nt][r] = 0.f;

#pragma unroll
        for (int ks = 0; ks < 8; ks++) {
            const int kk = ks * 8;
            float qa0 = Qs[(wb + g) * PADA + kk + tig];
            float qa1 = Qs[(wb + g + 8) * PADA + kk + tig];
            float qa2 = Qs[(wb + g) * PADA + kk + tig + 4];
            float qa3 = Qs[(wb + g + 8) * PADA + kk + tig + 4];
            uint32_t ah0 = f2tf32(qa0), ah1 = f2tf32(qa1);
            uint32_t ah2 = f2tf32(qa2), ah3 = f2tf32(qa3);
            uint32_t al0 = f2tf32(qa0 - __uint_as_float(ah0));
            uint32_t al1 = f2tf32(qa1 - __uint_as_float(ah1));
            uint32_t al2 = f2tf32(qa2 - __uint_as_float(ah2));
            uint32_t al3 = f2tf32(qa3 - __uint_as_float(ah3));
#pragma unroll
            for (int nt = 0; nt < 8; nt++) {
                float kb0v = Ks[(nt * 8 + g) * PADA + kk + tig];
                float kb1v = Ks[(nt * 8 + g) * PADA + kk + tig + 4];
                uint32_t bh0 = f2tf32(kb0v), bh1 = f2tf32(kb1v);
                uint32_t bl0 = f2tf32(kb0v - __uint_as_float(bh0));
                uint32_t bl1 = f2tf32(kb1v - __uint_as_float(bh1));
                mma_tf32(s[nt][0], s[nt][1], s[nt][2], s[nt][3],
                         ah0, ah1, ah2, ah3, bl0, bl1);
                mma_tf32(s[nt][0], s[nt][1], s[nt][2], s[nt][3],
                         al0, al1, al2, al3, bh0, bh1);
                mma_tf32(s[nt][0], s[nt][1], s[nt][2], s[nt][3],
                         ah0, ah1, ah2, ah3, bh0, bh1);
            }
        }

        // ---- fragment online softmax (rows g and g+8 of this warp) ----
        float rmax0 = -1e30f, rmax1 = -1e30f;
#pragma unroll
        for (int nt = 0; nt < 8; nt++) {
            rmax0 = fmaxf(rmax0, fmaxf(s[nt][0], s[nt][1]));
            rmax1 = fmaxf(rmax1, fmaxf(s[nt][2], s[nt][3]));
        }
        rmax0 = fmaxf(rmax0, __shfl_xor_sync(0xffffffffu, rmax0, 1));
        rmax0 = fmaxf(rmax0, __shfl_xor_sync(0xffffffffu, rmax0, 2));
        rmax1 = fmaxf(rmax1, __shfl_xor_sync(0xffffffffu, rmax1, 1));
        rmax1 = fmaxf(rmax1, __shfl_xor_sync(0xffffffffu, rmax1, 2));

        const float mn0 = fmaxf(m0, rmax0), mn1 = fmaxf(m1, rmax1);
        const float corr0 = __expf(m0 - mn0), corr1 = __expf(m1 - mn1);
        m0 = mn0; m1 = mn1;

        float ls0 = 0.f, ls1 = 0.f;
#pragma unroll
        for (int nt = 0; nt < 8; nt++) {
            s[nt][0] = __expf(s[nt][0] - mn0);
            s[nt][1] = __expf(s[nt][1] - mn0);
            s[nt][2] = __expf(s[nt][2] - mn1);
            s[nt][3] = __expf(s[nt][3] - mn1);
            ls0 += s[nt][0] + s[nt][1];
            ls1 += s[nt][2] + s[nt][3];
        }
        ls0 += __shfl_xor_sync(0xffffffffu, ls0, 1);
        ls0 += __shfl_xor_sync(0xffffffffu, ls0, 2);
        ls1 += __shfl_xor_sync(0xffffffffu, ls1, 1);
        ls1 += __shfl_xor_sync(0xffffffffu, ls1, 2);
        l0 = l0 * corr0 + ls0;
        l1 = l1 * corr1 + ls1;

        // ---- stage P in smem (warp-private rows) ----
        __syncwarp();
#pragma unroll
        for (int nt = 0; nt < 8; nt++) {
            *(float2*)&Ps[(wb + g) * PADA + nt * 8 + 2 * tig] =
                make_float2(s[nt][0], s[nt][1]);
            *(float2*)&Ps[(wb + g + 8) * PADA + nt * 8 + 2 * tig] =
                make_float2(s[nt][2], s[nt][3]);
        }
        __syncwarp();

        // rescale O
#pragma unroll
        for (int nt = 0; nt < 8; nt++) {
            o[nt][0] *= corr0; o[nt][1] *= corr0;
            o[nt][2] *= corr1; o[nt][3] *= corr1;
        }

        // ---- O += P V^T (plain tf32) ----
#pragma unroll
        for (int ks = 0; ks < 8; ks++) {
            const int kk = ks * 8;
            uint32_t a0 = f2tf32(Ps[(wb + g) * PADA + kk + tig]);
            uint32_t a1 = f2tf32(Ps[(wb + g + 8) * PADA + kk + tig]);
            uint32_t a2 = f2tf32(Ps[(wb + g) * PADA + kk + tig + 4]);
            uint32_t a3 = f2tf32(Ps[(wb + g + 8) * PADA + kk + tig + 4]);
#pragma unroll
            for (int nt = 0; nt < 8; nt++) {
                uint32_t b0 = f2tf32(Vt[(nt * 8 + g) * PADA + kk + tig]);
                uint32_t b1 = f2tf32(Vt[(nt * 8 + g) * PADA + kk + tig + 4]);
                mma_tf32(o[nt][0], o[nt][1], o[nt][2], o[nt][3],
                         a0, a1, a2, a3, b0, b1);
            }
        }
    }

    // ---- epilogue: normalize and store to g_o [b][s][h*64+d] ----
    const float il0 = 1.f / l0, il1 = 1.f / l1;
    const int r0 = q0 + wb + g, r1 = r0 + 8;
#pragma unroll
    for (int nt = 0; nt < 8; nt++) {
        const int col = h * HEAD_DIM + nt * 8 + 2 * tig;
        *(float2*)(g_o + ((size_t)b * SEQ + r0) * DMODEL + col) =
            make_float2(o[nt][0] * il0, o[nt][1] * il0);
        *(float2*)(g_o + ((size_t)b * SEQ + r1) * DMODEL + col) =
            make_float2(o[nt][2] * il1, o[nt][3] * il1);
    }
}

// ---------------------------------------------------------------------------

extern "C" void kernel_launch(void* const* d_in, const int* in_sizes, int n_in,
                              void* d_out, int out_size) {
    (void)in_sizes; (void)n_in; (void)out_size;
    const float* x      = (const float*)d_in[0];
    const float* w_qkv  = (const float*)d_in[1];
    const float* b_qkv  = (const float*)d_in[2];
    const float* w_proj = (const float*)d_in[3];
    const float* b_proj = (const float*)d_in[4];
    float* out = (float*)d_out;

    cudaFuncSetAttribute(gemm_mma, cudaFuncAttributeMaxDynamicSharedMemorySize,
                         GEMM_SMEM_BYTES);
    cudaFuncSetAttribute(attn_mma, cudaFuncAttributeMaxDynamicSharedMemorySize,
                         ATTN_SMEM_BYTES);

    transpose_kernel<<<dim3(96, 32), dim3(32, 8)>>>(w_qkv, 3072, 0);
    transpose_kernel<<<dim3(32, 32), dim3(32, 8)>>>(w_proj, 1024, 1);

    gemm_mma<<<dim3(24, 64), 256, GEMM_SMEM_BYTES>>>(x, b_qkv, nullptr, 0);

    attn_mma<<<dim3(SEQ / 128, NB_HEADS, BATCH), 256, ATTN_SMEM_BYTES>>>();

    gemm_mma<<<dim3(8, 64), 256, GEMM_SMEM_BYTES>>>(nullptr, b_proj, out, 1);
}

// round 7
// speedup vs baseline: 2.7592x; 1.0298x over previous
#include <cuda_runtime.h>
#include <cuda.h>
#include <cstdint>
#include <math.h>

// ---------------------------------------------------------------------------
// ViT MHA B=8, S=1024, D=1024, H=16, hd=64 (fp32 in/out).
// R6: attention with pre-converted tf32 operands in smem (cvt hoisted out of
//     mma loops), double-buffered cp.async K/V staging. GEMMs as in R4/R5.
// ---------------------------------------------------------------------------

#define NB_HEADS 16
#define HEAD_DIM 64
#define SEQ 1024
#define BATCH 8
#define DMODEL 1024

__device__ float g_q[(size_t)BATCH * NB_HEADS * SEQ * HEAD_DIM];
__device__ float g_k[(size_t)BATCH * NB_HEADS * SEQ * HEAD_DIM];
__device__ float g_v[(size_t)BATCH * NB_HEADS * SEQ * HEAD_DIM];
__device__ float g_o[(size_t)BATCH * SEQ * DMODEL];
__device__ float g_wqkvT[(size_t)3072 * 1024];   // [N][K] K-major
__device__ float g_wprojT[(size_t)1024 * 1024];  // [N][K] K-major

// ------------------------------ helpers ------------------------------------
__device__ __forceinline__ uint32_t smem_u32(const void* p) {
    uint32_t a;
    asm("{ .reg .u64 t; cvta.to.shared.u64 t, %1; cvt.u32.u64 %0, t; }"
        : "=r"(a) : "l"(p));
    return a;
}

__device__ __forceinline__ uint32_t f2tf32(float f) {
    uint32_t u;
    asm("cvt.rna.tf32.f32 %0, %1;" : "=r"(u) : "f"(f));
    return u;
}

__device__ __forceinline__ void cp_async16(uint32_t dst, const void* src) {
    asm volatile("cp.async.ca.shared.global [%0], [%1], 16;"
                 :: "r"(dst), "l"(src) : "memory");
}
__device__ __forceinline__ void cp_commit() {
    asm volatile("cp.async.commit_group;" ::: "memory");
}
__device__ __forceinline__ void cp_wait0() {
    asm volatile("cp.async.wait_group 0;" ::: "memory");
}
__device__ __forceinline__ void cp_wait1() {
    asm volatile("cp.async.wait_group 1;" ::: "memory");
}

__device__ __forceinline__ void mma_tf32(float& c0, float& c1, float& c2, float& c3,
                                         uint32_t a0, uint32_t a1, uint32_t a2,
                                         uint32_t a3, uint32_t b0, uint32_t b1) {
    asm volatile(
        "mma.sync.aligned.m16n8k8.row.col.f32.tf32.tf32.f32 "
        "{%0,%1,%2,%3}, {%4,%5,%6,%7}, {%8,%9}, {%0,%1,%2,%3};"
        : "+f"(c0), "+f"(c1), "+f"(c2), "+f"(c3)
        : "r"(a0), "r"(a1), "r"(a2), "r"(a3), "r"(b0), "r"(b1));
}

// ---------------------------------------------------------------------------
// Weight transpose: out[n][k] = in[k][n].  in is [1024][C].
// ---------------------------------------------------------------------------
__global__ __launch_bounds__(256) void transpose_kernel(const float* __restrict__ in,
                                                        int C, int which) {
    __shared__ float t[32][33];
    float* out = which ? g_wprojT : g_wqkvT;
    const int R = 1024;
    const int c0 = blockIdx.x * 32, r0 = blockIdx.y * 32;
    const int tx = threadIdx.x, ty = threadIdx.y;  // 32 x 8
#pragma unroll
    for (int i = 0; i < 32; i += 8)
        t[ty + i][tx] = in[(size_t)(r0 + ty + i) * C + c0 + tx];
    __syncthreads();
#pragma unroll
    for (int i = 0; i < 32; i += 8)
        out[(size_t)(c0 + ty + i) * R + r0 + tx] = t[tx][ty + i];
}

// ---------------------------------------------------------------------------
// mma.sync tf32 GEMM (unchanged, verified): C[128x128] = A x BT^T, K=1024.
// ---------------------------------------------------------------------------
#define PAD 36
#define GEMM_SMEM_BYTES (2 * 2 * 128 * PAD * 4)

__global__ __launch_bounds__(256) void gemm_mma(const float* __restrict__ A_ext,
                                                const float* __restrict__ bias,
                                                float* __restrict__ Cout, int mode) {
    extern __shared__ __align__(16) float sm[];
    float* As = sm;
    float* Bs = sm + 2 * 128 * PAD;
    const uint32_t sA = smem_u32(As), sB = smem_u32(Bs);

    const float* A  = mode ? g_o      : A_ext;
    const float* BT = mode ? g_wprojT : g_wqkvT;

    const int m0 = blockIdx.y * 128;
    const int n0 = blockIdx.x * 128;
    const int tid = threadIdx.x;
    const int warp = tid >> 5, lane = tid & 31;
    const int g = lane >> 2, tig = lane & 3;
    const int wm = (warp >> 2) * 64;
    const int wn = (warp & 3) * 32;

    float c[4][4][4];
#pragma unroll
    for (int i = 0; i < 4; i++)
#pragma unroll
        for (int j = 0; j < 4; j++)
#pragma unroll
            for (int r = 0; r < 4; r++) c[i][j][r] = 0.f;

    auto prefetch = [&](int buf, int kc) {
        const float* Ag = A  + (size_t)m0 * 1024 + kc * 32;
        const float* Bg = BT + (size_t)n0 * 1024 + kc * 32;
        const uint32_t aBase = sA + buf * 128 * PAD * 4;
        const uint32_t bBase = sB + buf * 128 * PAD * 4;
#pragma unroll
        for (int i = 0; i < 4; i++) {
            const int idx = tid + i * 256;
            const int row = idx >> 3, c4 = idx & 7;
            const uint32_t so = (uint32_t)(row * PAD + c4 * 4) * 4;
            cp_async16(aBase + so, Ag + (size_t)row * 1024 + c4 * 4);
            cp_async16(bBase + so, Bg + (size_t)row * 1024 + c4 * 4);
        }
        cp_commit();
    };

    prefetch(0, 0);

    for (int kc = 0; kc < 32; kc++) {
        const int p = kc & 1;
        cp_wait0();
        __syncthreads();
        if (kc < 31) prefetch(p ^ 1, kc + 1);

        const float* Ab = As + p * 128 * PAD;
        const float* Bb = Bs + p * 128 * PAD;

#pragma unroll
        for (int ks = 0; ks < 4; ks++) {
            const int kk = ks * 8;
            uint32_t a[4][4], b[4][2];
#pragma unroll
            for (int mt = 0; mt < 4; mt++) {
                const int r0 = wm + mt * 16 + g;
                a[mt][0] = f2tf32(Ab[r0 * PAD + kk + tig]);
                a[mt][1] = f2tf32(Ab[(r0 + 8) * PAD + kk + tig]);
                a[mt][2] = f2tf32(Ab[r0 * PAD + kk + tig + 4]);
                a[mt][3] = f2tf32(Ab[(r0 + 8) * PAD + kk + tig + 4]);
            }
#pragma unroll
            for (int nt = 0; nt < 4; nt++) {
                const int nr = wn + nt * 8 + g;
                b[nt][0] = f2tf32(Bb[nr * PAD + kk + tig]);
                b[nt][1] = f2tf32(Bb[nr * PAD + kk + tig + 4]);
            }
#pragma unroll
            for (int mt = 0; mt < 4; mt++)
#pragma unroll
                for (int nt = 0; nt < 4; nt++)
                    mma_tf32(c[mt][nt][0], c[mt][nt][1], c[mt][nt][2], c[mt][nt][3],
                             a[mt][0], a[mt][1], a[mt][2], a[mt][3],
                             b[nt][0], b[nt][1]);
        }
        __syncthreads();
    }

#pragma unroll
    for (int mt = 0; mt < 4; mt++) {
#pragma unroll
        for (int nt = 0; nt < 4; nt++) {
            const int rowA = m0 + wm + mt * 16 + g;
            const int rowB = rowA + 8;
            const int n = n0 + wn + nt * 8 + 2 * tig;
            const float b0 = bias[n], b1 = bias[n + 1];
            if (mode == 1) {
                *(float2*)(Cout + (size_t)rowA * 1024 + n) =
                    make_float2(c[mt][nt][0] + b0, c[mt][nt][1] + b1);
                *(float2*)(Cout + (size_t)rowB * 1024 + n) =
                    make_float2(c[mt][nt][2] + b0, c[mt][nt][3] + b1);
            } else {
                const int which = n >> 10;
                const int nm = n & 1023;
                const int h = nm >> 6, dd = nm & 63;
                float* dst = (which == 0) ? g_q : (which == 1) ? g_k : g_v;
                const float sc = (which == 0) ? 0.125f : 1.f;
                const int bA = rowA >> 10, sAr = rowA & 1023;
                const int bB = rowB >> 10, sBr = rowB & 1023;
                const size_t offA =
                    (((size_t)(bA * NB_HEADS + h) * SEQ) + sAr) * HEAD_DIM + dd;
                const size_t offB =
                    (((size_t)(bB * NB_HEADS + h) * SEQ) + sBr) * HEAD_DIM + dd;
                *(float2*)(dst + offA) =
                    make_float2((c[mt][nt][0] + b0) * sc, (c[mt][nt][1] + b1) * sc);
                *(float2*)(dst + offB) =
                    make_float2((c[mt][nt][2] + b0) * sc, (c[mt][nt][3] + b1) * sc);
            }
        }
    }
}

// ---------------------------------------------------------------------------
// Tensor-core flash attention, R6: all operands pre-converted to tf32 in smem.
// Block = (128 queries) x (b,h). 256 threads / 8 warps, warp owns 16 q-rows.
// Smem (uint32 words, PADA=68):
//   Qh[128][68], Ql[128][68]   : split-tf32 Q (converted once)
//   Kh[64][68],  Kl[64][68]    : split-tf32 K (converted per tile)
//   Vt[64][68]                 : tf32 V transposed (d, key)
//   Ps[128][68]                : tf32 P (also raw-Q staging in prologue)
//   St[2][128][68]             : raw K/V cp.async staging (double buffer)
// ---------------------------------------------------------------------------
#define PADA 68
#define OFF_QH 0
#define OFF_QL (128 * PADA)
#define OFF_KH (2 * 128 * PADA)
#define OFF_KL (OFF_KH + 64 * PADA)
#define OFF_VT (OFF_KL + 64 * PADA)
#define OFF_PS (OFF_VT + 64 * PADA)
#define OFF_ST (OFF_PS + 128 * PADA)
#define ATTN_SMEM_BYTES ((OFF_ST + 2 * 128 * PADA) * 4)

__global__ __launch_bounds__(256, 1) void attn_mma() {
    extern __shared__ __align__(16) uint32_t smw[];
    uint32_t* Qh = smw + OFF_QH;
    uint32_t* Ql = smw + OFF_QL;
    uint32_t* Kh = smw + OFF_KH;
    uint32_t* Kl = smw + OFF_KL;
    uint32_t* Vt = smw + OFF_VT;
    uint32_t* Ps = smw + OFF_PS;
    float* St[2] = {(float*)(smw + OFF_ST), (float*)(smw + OFF_ST + 128 * PADA)};

    const int tid = threadIdx.x;
    const int warp = tid >> 5, lane = tid & 31;
    const int g = lane >> 2, tig = lane & 3;
    const int wb = warp * 16;

    const int q0 = blockIdx.x * 128;
    const int h = blockIdx.y, b = blockIdx.z;
    const size_t bh = (size_t)(b * NB_HEADS + h) * SEQ * HEAD_DIM;
    const float* qb = g_q + bh;
    const float* kb = g_k + bh;
    const float* vb = g_v + bh;

    auto issue_tile = [&](int k0, float* Stp) {
        const uint32_t sSt = smem_u32(Stp);
#pragma unroll
        for (int i = 0; i < 4; i++) {  // K rows 0..63
            const int idx = tid + i * 256;
            const int row = idx >> 4, c4 = idx & 15;
            cp_async16(sSt + (uint32_t)(row * PADA + c4 * 4) * 4,
                       kb + (size_t)(k0 + row) * 64 + c4 * 4);
        }
#pragma unroll
        for (int i = 0; i < 4; i++) {  // V rows -> staging rows 64..127
            const int idx = tid + i * 256;
            const int row = idx >> 4, c4 = idx & 15;
            cp_async16(sSt + (uint32_t)((64 + row) * PADA + c4 * 4) * 4,
                       vb + (size_t)(k0 + row) * 64 + c4 * 4);
        }
        cp_commit();
    };

    // ---- prologue: stage raw Q into Ps region, prefetch tile 0 ----
    {
        float* Qstage = (float*)Ps;
        const uint32_t sQst = smem_u32(Qstage);
#pragma unroll
        for (int i = 0; i < 8; i++) {
            const int idx = tid + i * 256;
            const int row = idx >> 4, c4 = idx & 15;
            cp_async16(sQst + (uint32_t)(row * PADA + c4 * 4) * 4,
                       qb + (size_t)(q0 + row) * 64 + c4 * 4);
        }
        cp_commit();
        issue_tile(0, St[0]);
        cp_wait1();  // Q staged (tile0 may still be in flight)
        __syncthreads();
        // convert Q -> Qh/Ql (split tf32)
#pragma unroll
        for (int i = 0; i < 8; i++) {
            const int idx = tid + i * 256;
            const int row = idx >> 4, c4 = idx & 15;
            const float4 v = *(const float4*)&Qstage[row * PADA + c4 * 4];
            const int o4 = row * PADA + c4 * 4;
            uint32_t h0 = f2tf32(v.x), h1 = f2tf32(v.y);
            uint32_t h2 = f2tf32(v.z), h3 = f2tf32(v.w);
            // lows first (reads of Qstage row done before Qh alias? Qh != Ps, fine)
            Ql[o4 + 0] = f2tf32(v.x - __uint_as_float(h0));
            Ql[o4 + 1] = f2tf32(v.y - __uint_as_float(h1));
            Ql[o4 + 2] = f2tf32(v.z - __uint_as_float(h2));
            Ql[o4 + 3] = f2tf32(v.w - __uint_as_float(h3));
            Qh[o4 + 0] = h0; Qh[o4 + 1] = h1; Qh[o4 + 2] = h2; Qh[o4 + 3] = h3;
        }
    }

    float o[8][4];
#pragma unroll
    for (int nt = 0; nt < 8; nt++)
#pragma unroll
        for (int r = 0; r < 4; r++) o[nt][r] = 0.f;
    float m0 = -1e30f, m1 = -1e30f, l0 = 0.f, l1 = 0.f;

    for (int kb0 = 0; kb0 < 16; kb0++) {
        const int p = kb0 & 1;
        float* Stc = St[p];
        cp_wait0();       // current tile staged
        __syncthreads();  // prev iter PV reads of Ps/Vt done; Q convert visible

        // ---- convert K tile: raw -> Kh/Kl ----
#pragma unroll
        for (int i = 0; i < 4; i++) {
            const int idx = tid + i * 256;
            const int row = idx & 63, c4 = idx >> 6;
            const float4 v = *(const float4*)&Stc[row * PADA + c4 * 4];
            const int o4 = row * PADA + c4 * 4;
            uint32_t h0 = f2tf32(v.x), h1 = f2tf32(v.y);
            uint32_t h2 = f2tf32(v.z), h3 = f2tf32(v.w);
            Kl[o4 + 0] = f2tf32(v.x - __uint_as_float(h0));
            Kl[o4 + 1] = f2tf32(v.y - __uint_as_float(h1));
            Kl[o4 + 2] = f2tf32(v.z - __uint_as_float(h2));
            Kl[o4 + 3] = f2tf32(v.w - __uint_as_float(h3));
            Kh[o4 + 0] = h0; Kh[o4 + 1] = h1; Kh[o4 + 2] = h2; Kh[o4 + 3] = h3;
        }
        // ---- convert V tile: raw -> Vt (transposed, plain tf32) ----
#pragma unroll
        for (int i = 0; i < 4; i++) {
            const int idx = tid + i * 256;
            const int row = idx & 63, c4 = idx >> 6;
            const float4 v = *(const float4*)&Stc[(64 + row) * PADA + c4 * 4];
            Vt[(c4 * 4 + 0) * PADA + row] = f2tf32(v.x);
            Vt[(c4 * 4 + 1) * PADA + row] = f2tf32(v.y);
            Vt[(c4 * 4 + 2) * PADA + row] = f2tf32(v.z);
            Vt[(c4 * 4 + 3) * PADA + row] = f2tf32(v.w);
        }

        if (kb0 < 15) issue_tile((kb0 + 1) * 64, St[p ^ 1]);
        __syncthreads();  // conversions visible to all warps

        // ---- S = Q K^T (split-tf32: h*l + l*h + h*h) ----
        float s[8][4];
#pragma unroll
        for (int nt = 0; nt < 8; nt++)
#pragma unroll
            for (int r = 0; r < 4; r++) s[nt][r] = 0.f;

#pragma unroll
        for (int ks = 0; ks < 8; ks++) {
            const int kk = ks * 8;
            const int ra = (wb + g) * PADA + kk + tig;
            const int rb = (wb + g + 8) * PADA + kk + tig;
            uint32_t ah0 = Qh[ra], ah1 = Qh[rb], ah2 = Qh[ra + 4], ah3 = Qh[rb + 4];
            uint32_t al0 = Ql[ra], al1 = Ql[rb], al2 = Ql[ra + 4], al3 = Ql[rb + 4];
#pragma unroll
            for (int nt = 0; nt < 8; nt++) {
                const int kr = (nt * 8 + g) * PADA + kk + tig;
                uint32_t bh0 = Kh[kr], bh1 = Kh[kr + 4];
                uint32_t bl0 = Kl[kr], bl1 = Kl[kr + 4];
                mma_tf32(s[nt][0], s[nt][1], s[nt][2], s[nt][3],
                         ah0, ah1, ah2, ah3, bl0, bl1);
                mma_tf32(s[nt][0], s[nt][1], s[nt][2], s[nt][3],
                         al0, al1, al2, al3, bh0, bh1);
                mma_tf32(s[nt][0], s[nt][1], s[nt][2], s[nt][3],
                         ah0, ah1, ah2, ah3, bh0, bh1);
            }
        }

        // ---- fragment online softmax ----
        float rmax0 = -1e30f, rmax1 = -1e30f;
#pragma unroll
        for (int nt = 0; nt < 8; nt++) {
            rmax0 = fmaxf(rmax0, fmaxf(s[nt][0], s[nt][1]));
            rmax1 = fmaxf(rmax1, fmaxf(s[nt][2], s[nt][3]));
        }
        rmax0 = fmaxf(rmax0, __shfl_xor_sync(0xffffffffu, rmax0, 1));
        rmax0 = fmaxf(rmax0, __shfl_xor_sync(0xffffffffu, rmax0, 2));
        rmax1 = fmaxf(rmax1, __shfl_xor_sync(0xffffffffu, rmax1, 1));
        rmax1 = fmaxf(rmax1, __shfl_xor_sync(0xffffffffu, rmax1, 2));

        const float mn0 = fmaxf(m0, rmax0), mn1 = fmaxf(m1, rmax1);
        const float corr0 = __expf(m0 - mn0), corr1 = __expf(m1 - mn1);
        m0 = mn0; m1 = mn1;

        float ls0 = 0.f, ls1 = 0.f;
#pragma unroll
        for (int nt = 0; nt < 8; nt++) {
            s[nt][0] = __expf(s[nt][0] - mn0);
            s[nt][1] = __expf(s[nt][1] - mn0);
            s[nt][2] = __expf(s[nt][2] - mn1);
            s[nt][3] = __expf(s[nt][3] - mn1);
            ls0 += s[nt][0] + s[nt][1];
            ls1 += s[nt][2] + s[nt][3];
        }
        ls0 += __shfl_xor_sync(0xffffffffu, ls0, 1);
        ls0 += __shfl_xor_sync(0xffffffffu, ls0, 2);
        ls1 += __shfl_xor_sync(0xffffffffu, ls1, 1);
        ls1 += __shfl_xor_sync(0xffffffffu, ls1, 2);
        l0 = l0 * corr0 + ls0;
        l1 = l1 * corr1 + ls1;

        // ---- stage P (tf32) in smem; warp-private rows ----
#pragma unroll
        for (int nt = 0; nt < 8; nt++) {
            *(uint2*)&Ps[(wb + g) * PADA + nt * 8 + 2 * tig] =
                make_uint2(f2tf32(s[nt][0]), f2tf32(s[nt][1]));
            *(uint2*)&Ps[(wb + g + 8) * PADA + nt * 8 + 2 * tig] =
                make_uint2(f2tf32(s[nt][2]), f2tf32(s[nt][3]));
        }
        __syncwarp();

        // rescale O
#pragma unroll
        for (int nt = 0; nt < 8; nt++) {
            o[nt][0] *= corr0; o[nt][1] *= corr0;
            o[nt][2] *= corr1; o[nt][3] *= corr1;
        }

        // ---- O += P V^T (plain tf32) ----
#pragma unroll
        for (int ks = 0; ks < 8; ks++) {
            const int kk = ks * 8;
            const int ra = (wb + g) * PADA + kk + tig;
            const int rb = (wb + g + 8) * PADA + kk + tig;
            uint32_t a0 = Ps[ra], a1 = Ps[rb], a2 = Ps[ra + 4], a3 = Ps[rb + 4];
#pragma unroll
            for (int nt = 0; nt < 8; nt++) {
                const int vr = (nt * 8 + g) * PADA + kk + tig;
                mma_tf32(o[nt][0], o[nt][1], o[nt][2], o[nt][3],
                         a0, a1, a2, a3, Vt[vr], Vt[vr + 4]);
            }
        }
    }

    // ---- epilogue: normalize and store to g_o [b][s][h*64+d] ----
    const float il0 = 1.f / l0, il1 = 1.f / l1;
    const int r0 = q0 + wb + g, r1 = r0 + 8;
#pragma unroll
    for (int nt = 0; nt < 8; nt++) {
        const int col = h * HEAD_DIM + nt * 8 + 2 * tig;
        *(float2*)(g_o + ((size_t)b * SEQ + r0) * DMODEL + col) =
            make_float2(o[nt][0] * il0, o[nt][1] * il0);
        *(float2*)(g_o + ((size_t)b * SEQ + r1) * DMODEL + col) =
            make_float2(o[nt][2] * il1, o[nt][3] * il1);
    }
}

// ---------------------------------------------------------------------------

extern "C" void kernel_launch(void* const* d_in, const int* in_sizes, int n_in,
                              void* d_out, int out_size) {
    (void)in_sizes; (void)n_in; (void)out_size;
    const float* x      = (const float*)d_in[0];
    const float* w_qkv  = (const float*)d_in[1];
    const float* b_qkv  = (const float*)d_in[2];
    const float* w_proj = (const float*)d_in[3];
    const float* b_proj = (const float*)d_in[4];
    float* out = (float*)d_out;

    cudaFuncSetAttribute(gemm_mma, cudaFuncAttributeMaxDynamicSharedMemorySize,
                         GEMM_SMEM_BYTES);
    cudaFuncSetAttribute(attn_mma, cudaFuncAttributeMaxDynamicSharedMemorySize,
                         ATTN_SMEM_BYTES);

    transpose_kernel<<<dim3(96, 32), dim3(32, 8)>>>(w_qkv, 3072, 0);
    transpose_kernel<<<dim3(32, 32), dim3(32, 8)>>>(w_proj, 1024, 1);

    gemm_mma<<<dim3(24, 64), 256, GEMM_SMEM_BYTES>>>(x, b_qkv, nullptr, 0);

    attn_mma<<<dim3(SEQ / 128, NB_HEADS, BATCH), 256, ATTN_SMEM_BYTES>>>();

    gemm_mma<<<dim3(8, 64), 256, GEMM_SMEM_BYTES>>>(nullptr, b_proj, out, 1);
}